// round 6
// baseline (speedup 1.0000x reference)
#include <cuda_runtime.h>
#include <cuda_bf16.h>
#include <cstdint>
#include <math.h>

#define HIDDEN 2048
#define SEQ    2048
#define NH     32
#define QKV_COLS 768   // 256 q | 256 k | 256 v
#define CDIM   256     // N_HEADS * V_BITS

// ---------------- scratch (static device, no allocations) ----------------
__device__ float g_qkv[SEQ * QKV_COLS];     // tanh(q) | tanh(k) | sigmoid(v)
__device__ float g_z[SEQ * CDIM];           // emb-interpolated attn out (tf32-rounded)
__device__ float g_gate[SEQ * HIDDEN];      // sigmoid(hs @ Wg^T)
// tf32-prerounded copies of GEMM inputs
__device__ float g_hsr[SEQ * HIDDEN];
__device__ float g_wgr[HIDDEN * HIDDEN];
__device__ float g_wqkvr[QKV_COLS * HIDDEN];  // Wq | Wk | Wv concatenated
__device__ float g_wor[HIDDEN * CDIM];

// ---------------- helpers ----------------
__device__ __forceinline__ float f2tf32(float x) {
    uint32_t u;
    asm("cvt.rna.tf32.f32 %0, %1;" : "=r"(u) : "f"(x));
    return __uint_as_float(u);
}

__device__ __forceinline__ void mma8(float* c, const uint32_t* a, const uint32_t* b) {
    asm volatile(
        "mma.sync.aligned.m16n8k8.row.col.f32.tf32.tf32.f32 "
        "{%0,%1,%2,%3}, {%4,%5,%6,%7}, {%8,%9}, {%0,%1,%2,%3};\n"
        : "+f"(c[0]), "+f"(c[1]), "+f"(c[2]), "+f"(c[3])
        : "r"(a[0]), "r"(a[1]), "r"(a[2]), "r"(a[3]), "r"(b[0]), "r"(b[1]));
}

__device__ __forceinline__ void ldsm4(uint32_t* d, uint32_t addr) {
    asm volatile("ldmatrix.sync.aligned.m8n8.x4.shared.b16 {%0,%1,%2,%3}, [%4];"
                 : "=r"(d[0]), "=r"(d[1]), "=r"(d[2]), "=r"(d[3]) : "r"(addr));
}

__device__ __forceinline__ void cp16(uint32_t dst, const void* src) {
    asm volatile("cp.async.cg.shared.global [%0], [%1], 16;" :: "r"(dst), "l"(src));
}
__device__ __forceinline__ void cp_commit() { asm volatile("cp.async.commit_group;"); }
template <int N>
__device__ __forceinline__ void cp_wait() { asm volatile("cp.async.wait_group %0;" :: "n"(N)); }

__device__ __forceinline__ float sigm(float x) { return 1.0f / (1.0f + expf(-x)); }

// ---------------- GEMM (NT: C[M,N] = A[M,K] * B[N,K]^T) ----------------
// CTA tile 128x128x32, 8 warps (2x4), warp tile 64x32, m16n8k8 tf32.
// 3-stage cp.async pipeline in dynamic smem; inputs already tf32-rounded.
constexpr int BM = 128, BN = 128, BK = 32;
constexpr int WM = 64,  WN = 32;
constexpr int STAGEB = BM * BK * 4;              // 16384 bytes per stage per operand
constexpr int SMEM_TOTAL = 3 * STAGEB * 2;       // 98304 bytes

extern __shared__ float smem_dyn[];

__device__ __forceinline__ void gemm_mainloop(
    const float* __restrict__ Ap, int lda,
    const float* __restrict__ Bp, int ldb,
    int mloc, int nloc, int K, float acc[4][4][4]) {

    const int tid  = threadIdx.x;
    const int warp = tid >> 5, lane = tid & 31;
    const int wm = warp & 1, wn = warp >> 1;

    const uint32_t sAb = (uint32_t)__cvta_generic_to_shared(&smem_dyn[0]);
    const uint32_t sBb = sAb + 3 * STAGEB;

    // ---- producer mapping: row = tid>>1 (0..127), float4 cols pc0..pc0+3 ----
    const int prow = tid >> 1;
    const int pc0  = (tid & 1) * 4;
    const float* gA = Ap + (size_t)(mloc + prow) * lda + pc0 * 4;
    const float* gB = Bp + (size_t)(nloc + prow) * ldb + pc0 * 4;
    uint32_t pOff[4];
#pragma unroll
    for (int i = 0; i < 4; i++) {
        const int c = pc0 + i;
        pOff[i] = (uint32_t)(prow * 128 + ((c ^ (prow & 7)) * 16));
    }

    // ---- consumer (ldmatrix) lane addressing ----
    const int l7    = lane & 7;
    const int a_row = l7 + ((lane >> 3) & 1) * 8;
    const int a_hb  = lane >> 4;              // k-half within 8-k group
    const int b_row = l7 + (lane >> 4) * 8;
    const int b_hb  = (lane >> 3) & 1;
    uint32_t aBase[4], bBase[2];
#pragma unroll
    for (int mt = 0; mt < 4; mt++)
        aBase[mt] = sAb + (uint32_t)((wm * WM + mt * 16 + a_row) * 128);
#pragma unroll
    for (int p = 0; p < 2; p++)
        bBase[p] = sBb + (uint32_t)((wn * WN + p * 16 + b_row) * 128);

    const int nk = K / BK;

    // prologue: tiles 0,1 into stages 0,1
#pragma unroll
    for (int p = 0; p < 2; p++) {
        const int off = p * BK;
        const uint32_t sb = (uint32_t)(p * STAGEB);
#pragma unroll
        for (int i = 0; i < 4; i++) {
            cp16(sAb + sb + pOff[i], gA + off + i * 4);
            cp16(sBb + sb + pOff[i], gB + off + i * 4);
        }
        cp_commit();
    }

    int st = 0;
    for (int kt = 0; kt < nk; kt++) {
        cp_wait<1>();
        __syncthreads();
        const uint32_t abuf = (uint32_t)(st * STAGEB);
#pragma unroll
        for (int ks = 0; ks < 4; ks++) {        // 4 x k8 groups within BK=32
            uint32_t afr[4][4];
            uint32_t bfr[2][4];
            const uint32_t aslot = (uint32_t)((((2 * ks + a_hb) ^ l7) * 16));
            const uint32_t bslot = (uint32_t)((((2 * ks + b_hb) ^ l7) * 16));
#pragma unroll
            for (int mt = 0; mt < 4; mt++)
                ldsm4(afr[mt], aBase[mt] + abuf + aslot);
#pragma unroll
            for (int p = 0; p < 2; p++)
                ldsm4(bfr[p], bBase[p] + abuf + bslot);
#pragma unroll
            for (int mt = 0; mt < 4; mt++)
#pragma unroll
                for (int nt = 0; nt < 4; nt++)
                    mma8(acc[mt][nt], afr[mt], &bfr[nt >> 1][(nt & 1) * 2]);
        }
        if (kt + 2 < nk) {
            int stp = st + 2; if (stp >= 3) stp -= 3;
            const int off = (kt + 2) * BK;
            const uint32_t sb = (uint32_t)(stp * STAGEB);
#pragma unroll
            for (int i = 0; i < 4; i++) {
                cp16(sAb + sb + pOff[i], gA + off + i * 4);
                cp16(sBb + sb + pOff[i], gB + off + i * 4);
            }
        }
        cp_commit();
        if (++st == 3) st = 0;
    }
}

// ---- fused QKV + GATE kernel ----
__global__ __launch_bounds__(256, 2)
void gemm_qkv_gate() {
    const int cid = blockIdx.x;
    const float* Bp;
    int nloc, mloc;
    bool is_gate;
    if (cid < 256) {                  // GATE: 16 x 16 tiles
        is_gate = true;
        nloc = (cid & 15) * BN;
        mloc = (cid >> 4) * BM;
        Bp = g_wgr;
    } else {                          // QKV: 6 x 16 tiles over concat [768,2048]
        is_gate = false;
        const int r = cid - 256;
        nloc = (r % 6) * BN;
        mloc = (r / 6) * BM;
        Bp = g_wqkvr;
    }

    float acc[4][4][4];
#pragma unroll
    for (int i = 0; i < 4; i++)
#pragma unroll
        for (int j = 0; j < 4; j++)
#pragma unroll
            for (int l = 0; l < 4; l++) acc[i][j][l] = 0.0f;

    gemm_mainloop(g_hsr, HIDDEN, Bp, HIDDEN, mloc, nloc, HIDDEN, acc);

    const int tid = threadIdx.x;
    const int warp = tid >> 5, lane = tid & 31;
    const int g = lane >> 2, t = lane & 3;
    const int wm = warp & 1, wn = warp >> 1;

#pragma unroll
    for (int mt = 0; mt < 4; mt++) {
#pragma unroll
        for (int nt = 0; nt < 4; nt++) {
            const int row0 = mloc + wm * WM + mt * 16 + g;
            const int col  = nloc + wn * WN + nt * 8 + 2 * t;
            const float* c = acc[mt][nt];
            if (is_gate) {
                float2 y0, y1;
                y0.x = sigm(c[0]); y0.y = sigm(c[1]);
                y1.x = sigm(c[2]); y1.y = sigm(c[3]);
                *(float2*)&g_gate[row0 * HIDDEN + col] = y0;
                *(float2*)&g_gate[(row0 + 8) * HIDDEN + col] = y1;
            } else {
                float2 y0, y1;
                if (col < 512) {
                    y0.x = tanhf(c[0]); y0.y = tanhf(c[1]);
                    y1.x = tanhf(c[2]); y1.y = tanhf(c[3]);
                } else {
                    y0.x = sigm(c[0]); y0.y = sigm(c[1]);
                    y1.x = sigm(c[2]); y1.y = sigm(c[3]);
                }
                *(float2*)&g_qkv[row0 * QKV_COLS + col] = y0;
                *(float2*)&g_qkv[(row0 + 8) * QKV_COLS + col] = y1;
            }
        }
    }
}

// ---- OUT kernel: out = (z @ Wo^T) * gate ----
__global__ __launch_bounds__(256, 2)
void gemm_out(float* __restrict__ Cout) {
    const int nloc = (blockIdx.x & 15) * BN;
    const int mloc = (blockIdx.x >> 4) * BM;

    float acc[4][4][4];
#pragma unroll
    for (int i = 0; i < 4; i++)
#pragma unroll
        for (int j = 0; j < 4; j++)
#pragma unroll
            for (int l = 0; l < 4; l++) acc[i][j][l] = 0.0f;

    gemm_mainloop(g_z, CDIM, g_wor, CDIM, mloc, nloc, CDIM, acc);

    const int tid = threadIdx.x;
    const int warp = tid >> 5, lane = tid & 31;
    const int g = lane >> 2, t = lane & 3;
    const int wm = warp & 1, wn = warp >> 1;

#pragma unroll
    for (int mt = 0; mt < 4; mt++) {
#pragma unroll
        for (int nt = 0; nt < 4; nt++) {
            const int row0 = mloc + wm * WM + mt * 16 + g;
            const int col  = nloc + wn * WN + nt * 8 + 2 * t;
            const float* c = acc[mt][nt];
            float2 gt0 = *(const float2*)&g_gate[row0 * HIDDEN + col];
            float2 gt1 = *(const float2*)&g_gate[(row0 + 8) * HIDDEN + col];
            float2 y0, y1;
            y0.x = c[0] * gt0.x; y0.y = c[1] * gt0.y;
            y1.x = c[2] * gt1.x; y1.y = c[3] * gt1.y;
            *(float2*)&Cout[row0 * HIDDEN + col] = y0;
            *(float2*)&Cout[(row0 + 8) * HIDDEN + col] = y1;
        }
    }
}

// ---------------- preround: copy inputs with tf32 (RNA) rounding ----------------
__global__ __launch_bounds__(256)
void preround(const float* __restrict__ hs, const float* __restrict__ Wq,
              const float* __restrict__ Wk, const float* __restrict__ Wv,
              const float* __restrict__ Wo, const float* __restrict__ Wg) {
    constexpr int N_HS = (SEQ * HIDDEN) / 4;          // 1048576
    constexpr int N_W  = (256 * HIDDEN) / 4;          // 131072
    constexpr int TOT  = N_HS * 2 + N_W * 4;          // hs, Wg, Wq, Wk, Wv, Wo

    for (int i = blockIdx.x * blockDim.x + threadIdx.x; i < TOT;
         i += gridDim.x * blockDim.x) {
        const float4* src;
        float4* dst;
        if (i < N_HS) {
            src = (const float4*)hs + i;            dst = (float4*)g_hsr + i;
        } else if (i < 2 * N_HS) {
            src = (const float4*)Wg + (i - N_HS);   dst = (float4*)g_wgr + (i - N_HS);
        } else {
            int j = i - 2 * N_HS;
            if (j < N_W)            { src = (const float4*)Wq + j;           dst = (float4*)g_wqkvr + j; }
            else if (j < 2 * N_W)   { src = (const float4*)Wk + (j - N_W);   dst = (float4*)g_wqkvr + j; }
            else if (j < 3 * N_W)   { src = (const float4*)Wv + (j - 2*N_W); dst = (float4*)g_wqkvr + j; }
            else                    { src = (const float4*)Wo + (j - 3*N_W); dst = (float4*)g_wor + (j - 3*N_W); }
        }
        float4 v = *src;
        v.x = f2tf32(v.x); v.y = f2tf32(v.y); v.z = f2tf32(v.z); v.w = f2tf32(v.w);
        *dst = v;
    }
}

// ---------------- windowed decayed-softmax attention ----------------
// decay 0.45 => bias -0.7985*dist; truncation at W=64 leaves < 1e-21 relative mass.
constexpr int WIN = 64, QB = 128;
constexpr int SROWS = QB + WIN - 1;   // 191
constexpr int PITCH = 9;              // conflict-free scalar smem reads

__global__ __launch_bounds__(128)
void attn_kernel(const float* __restrict__ e0, const float* __restrict__ e1) {
    __shared__ float ks[SROWS * PITCH];
    __shared__ float vs[SROWS * PITCH];

    const int h   = blockIdx.y;
    const int q0  = blockIdx.x * QB;
    const int tid = threadIdx.x;
    const int j0  = q0 - (WIN - 1);

    for (int idx = tid; idx < SROWS * 8; idx += 128) {
        const int r = idx >> 3, c = idx & 7;
        const int j = j0 + r;
        float kv = 0.0f, vv = 0.0f;
        if (j >= 0) {
            kv = g_qkv[j * QKV_COLS + 256 + h * 8 + c];
            vv = g_qkv[j * QKV_COLS + 512 + h * 8 + c];
        }
        ks[r * PITCH + c] = kv;
        vs[r * PITCH + c] = vv;
    }
    __syncthreads();

    const int i = q0 + tid;
    float q[8];
#pragma unroll
    for (int b = 0; b < 8; b++) q[b] = g_qkv[i * QKV_COLS + h * 8 + b];

    float num[8];
#pragma unroll
    for (int b = 0; b < 8; b++) num[b] = 0.0f;
    float den = 0.0f;

    const float LOGD = -0.7985077f;   // ln(0.45)
    const int dmax = (i < WIN - 1) ? i : (WIN - 1);

    for (int d = 0; d <= dmax; d++) {
        const int jj = (tid + (WIN - 1) - d) * PITCH;
        float dot = 0.0f;
#pragma unroll
        for (int b = 0; b < 8; b++) dot += q[b] * ks[jj + b];
        const float w = expf(dot * 0.125f + (float)d * LOGD);
        den += w;
#pragma unroll
        for (int b = 0; b < 8; b++) num[b] += w * vs[jj + b];
    }

    const float inv = 1.0f / den;
#pragma unroll
    for (int b = 0; b < 8; b++) {
        const int c = h * 8 + b;
        const float p = num[b] * inv;
        // write tf32-rounded so gemm_out can consume directly
        g_z[i * CDIM + c] = f2tf32(e1[c] * p + e0[c] * (1.0f - p));
    }
}

// ---------------- launch ----------------
extern "C" void kernel_launch(void* const* d_in, const int* in_sizes, int n_in,
                              void* d_out, int out_size) {
    const float* hs = (const float*)d_in[0];
    const float* Wq = (const float*)d_in[1];
    const float* Wk = (const float*)d_in[2];
    const float* Wv = (const float*)d_in[3];
    const float* Wo = (const float*)d_in[4];
    const float* Wg = (const float*)d_in[5];
    const float* e0 = (const float*)d_in[6];
    const float* e1 = (const float*)d_in[7];
    float* out = (float*)d_out;

    cudaFuncSetAttribute(gemm_qkv_gate, cudaFuncAttributeMaxDynamicSharedMemorySize, SMEM_TOTAL);
    cudaFuncSetAttribute(gemm_out,      cudaFuncAttributeMaxDynamicSharedMemorySize, SMEM_TOTAL);

    // 0) round all GEMM inputs to tf32 once
    preround<<<1024, 256>>>(hs, Wq, Wk, Wv, Wo, Wg);

    // 1) fused QKV projections (+activations) and gate GEMM (+sigmoid)
    gemm_qkv_gate<<<256 + 96, 256, SMEM_TOTAL>>>();

    // 2) windowed attention + value-embedding interpolation
    attn_kernel<<<dim3(SEQ / QB, NH), 128>>>(e0, e1);

    // 3) out = (z @ Wo^T) * gate
    gemm_out<<<256, 256, SMEM_TOTAL>>>(out);
}

// round 8
// speedup vs baseline: 1.0510x; 1.0510x over previous
#include <cuda_runtime.h>
#include <cuda_bf16.h>
#include <cstdint>
#include <math.h>

#define HIDDEN 2048
#define SEQ    2048
#define NH     32
#define QKV_COLS 768   // 256 q | 256 k | 256 v
#define CDIM   256     // N_HEADS * V_BITS

// ---------------- scratch (static device, no allocations) ----------------
__device__ float g_qkv[SEQ * QKV_COLS];     // tanh(q) | tanh(k) | sigmoid(v)
__device__ float g_z[SEQ * CDIM];           // emb-interpolated attn out (tf32-rounded)
__device__ float g_gate[SEQ * HIDDEN];      // sigmoid(hs @ Wg^T)
// tf32-prerounded copies of GEMM inputs
__device__ float g_hsr[SEQ * HIDDEN];
__device__ float g_wgr[HIDDEN * HIDDEN];
__device__ float g_wqkvr[QKV_COLS * HIDDEN];  // Wq | Wk | Wv concatenated
__device__ float g_wor[HIDDEN * CDIM];

// ---------------- helpers ----------------
__device__ __forceinline__ float f2tf32(float x) {
    uint32_t u;
    asm("cvt.rna.tf32.f32 %0, %1;" : "=r"(u) : "f"(x));
    return __uint_as_float(u);
}

__device__ __forceinline__ void mma8(float* c, const uint32_t* a, const uint32_t* b) {
    asm volatile(
        "mma.sync.aligned.m16n8k8.row.col.f32.tf32.tf32.f32 "
        "{%0,%1,%2,%3}, {%4,%5,%6,%7}, {%8,%9}, {%0,%1,%2,%3};\n"
        : "+f"(c[0]), "+f"(c[1]), "+f"(c[2]), "+f"(c[3])
        : "r"(a[0]), "r"(a[1]), "r"(a[2]), "r"(a[3]), "r"(b[0]), "r"(b[1]));
}

__device__ __forceinline__ void ldsm4(uint32_t* d, uint32_t addr) {
    asm volatile("ldmatrix.sync.aligned.m8n8.x4.shared.b16 {%0,%1,%2,%3}, [%4];"
                 : "=r"(d[0]), "=r"(d[1]), "=r"(d[2]), "=r"(d[3]) : "r"(addr));
}

__device__ __forceinline__ void cp16(uint32_t dst, const void* src) {
    asm volatile("cp.async.cg.shared.global [%0], [%1], 16;" :: "r"(dst), "l"(src));
}
__device__ __forceinline__ void cp_commit() { asm volatile("cp.async.commit_group;"); }
template <int N>
__device__ __forceinline__ void cp_wait() { asm volatile("cp.async.wait_group %0;" :: "n"(N)); }

__device__ __forceinline__ float sigm(float x) { return 1.0f / (1.0f + expf(-x)); }

// swizzle key: distinct permutation per row within each bank-parity class -> conflict-free
__device__ __forceinline__ int swkey(int r) { return (r & 3) ^ ((r & 4) >> 2); }

// ---------------- GEMM (NT: C[M,N] = A[M,K] * B[N,K]^T) ----------------
// CTA tile 64x128x16, 8 warps (2x4), warp tile 32x32, m16n8k8 tf32.
// 3-stage cp.async pipeline; inputs already tf32-rounded.
constexpr int BM = 64, BN = 128, BK = 16;
constexpr int ASTAGE = BM * BK * 4;   // 4096 B
constexpr int BSTAGE = BN * BK * 4;   // 8192 B

__device__ __forceinline__ void gemm_mainloop(
    float (*As)[BM * BK], float (*Bs)[BN * BK],
    const float* __restrict__ Ap, int lda,
    const float* __restrict__ Bp, int ldb,
    int mloc, int nloc, int K, float acc[2][4][4]) {

    const int tid  = threadIdx.x;
    const int warp = tid >> 5, lane = tid & 31;
    const int wm = warp & 1, wn = warp >> 1;

    // ---- producer mapping ----
    // A: 64 rows x 4 float4 -> 1 cp16/thread
    const int ar  = tid >> 2;       // 0..63
    const int ac4 = tid & 3;        // 0..3
    const float* gA = Ap + (size_t)(mloc + ar) * lda + ac4 * 4;
    const uint32_t sAb = (uint32_t)__cvta_generic_to_shared(&As[0][0]);
    const uint32_t sBb = (uint32_t)__cvta_generic_to_shared(&Bs[0][0]);
    const uint32_t saOff = (uint32_t)((ar * 4 + (ac4 ^ swkey(ar))) * 16);
    // B: 128 rows x 4 float4 -> 2 cp16/thread
    const int br  = tid >> 1;       // 0..127
    const int bc0 = (tid & 1) * 2;  // 0 or 2
    const float* gB0 = Bp + (size_t)(nloc + br) * ldb + bc0 * 4;
    const float* gB1 = gB0 + 4;
    const uint32_t sbOff0 = (uint32_t)((br * 4 + (bc0       ^ swkey(br))) * 16);
    const uint32_t sbOff1 = (uint32_t)((br * 4 + ((bc0 + 1) ^ swkey(br))) * 16);

    // ---- consumer (ldmatrix) lane addressing ----
    const int l7   = lane & 7;
    const int keyl = swkey(l7);
    const int a_row = l7 + ((lane >> 3) & 1) * 8;
    const int a_hb  = lane >> 4;
    const int b_row = l7 + (lane >> 4) * 8;
    const int b_hb  = (lane >> 3) & 1;
    uint32_t aBase[2], bBase[2];
#pragma unroll
    for (int mt = 0; mt < 2; mt++)
        aBase[mt] = sAb + (uint32_t)((wm * 32 + mt * 16 + a_row) * 64);
#pragma unroll
    for (int p = 0; p < 2; p++)
        bBase[p] = sBb + (uint32_t)((wn * 32 + p * 16 + b_row) * 64);

    const int nk = K / BK;

    // prologue: tiles 0,1 into stages 0,1
#pragma unroll
    for (int p = 0; p < 2; p++) {
        const int off = p * BK;
        cp16(sAb + (uint32_t)(p * ASTAGE) + saOff, gA + off);
        cp16(sBb + (uint32_t)(p * BSTAGE) + sbOff0, gB0 + off);
        cp16(sBb + (uint32_t)(p * BSTAGE) + sbOff1, gB1 + off);
        cp_commit();
    }

    int st = 0;
    for (int kt = 0; kt < nk; kt++) {
        cp_wait<1>();
        __syncthreads();
        const uint32_t aST = (uint32_t)(st * ASTAGE);
        const uint32_t bST = (uint32_t)(st * BSTAGE);
#pragma unroll
        for (int ks = 0; ks < 2; ks++) {
            uint32_t afr[2][4];
            uint32_t bfr[2][4];
            const uint32_t aslot = (uint32_t)(((2 * ks + a_hb) ^ keyl) * 16);
            const uint32_t bslot = (uint32_t)(((2 * ks + b_hb) ^ keyl) * 16);
#pragma unroll
            for (int mt = 0; mt < 2; mt++)
                ldsm4(afr[mt], aBase[mt] + aST + aslot);
#pragma unroll
            for (int p = 0; p < 2; p++)
                ldsm4(bfr[p], bBase[p] + bST + bslot);
#pragma unroll
            for (int mt = 0; mt < 2; mt++)
#pragma unroll
                for (int nt = 0; nt < 4; nt++)
                    mma8(acc[mt][nt], afr[mt], &bfr[nt >> 1][(nt & 1) * 2]);
        }
        if (kt + 2 < nk) {
            int stp = st + 2; if (stp >= 3) stp -= 3;
            const int off = (kt + 2) * BK;
            cp16(sAb + (uint32_t)(stp * ASTAGE) + saOff, gA + off);
            cp16(sBb + (uint32_t)(stp * BSTAGE) + sbOff0, gB0 + off);
            cp16(sBb + (uint32_t)(stp * BSTAGE) + sbOff1, gB1 + off);
        }
        cp_commit();
        if (++st == 3) st = 0;
    }
}

// ---- fused QKV + GATE kernel ----
__global__ __launch_bounds__(256, 3)
void gemm_qkv_gate() {
    __shared__ float As[3][BM * BK];
    __shared__ float Bs[3][BN * BK];

    const int cid = blockIdx.x;
    const float* Bp;
    int nloc, mloc;
    bool is_gate;
    if (cid < 512) {                  // GATE: 32 (m) x 16 (n) tiles
        is_gate = true;
        nloc = (cid & 15) * BN;
        mloc = (cid >> 4) * BM;
        Bp = g_wgr;
    } else {                          // QKV: 32 (m) x 6 (n) tiles over concat [768,2048]
        is_gate = false;
        const int r = cid - 512;
        nloc = (r % 6) * BN;
        mloc = (r / 6) * BM;
        Bp = g_wqkvr;
    }

    float acc[2][4][4];
#pragma unroll
    for (int i = 0; i < 2; i++)
#pragma unroll
        for (int j = 0; j < 4; j++)
#pragma unroll
            for (int l = 0; l < 4; l++) acc[i][j][l] = 0.0f;

    gemm_mainloop(As, Bs, g_hsr, HIDDEN, Bp, HIDDEN, mloc, nloc, HIDDEN, acc);

    const int tid = threadIdx.x;
    const int warp = tid >> 5, lane = tid & 31;
    const int g = lane >> 2, t = lane & 3;
    const int wm = warp & 1, wn = warp >> 1;

#pragma unroll
    for (int mt = 0; mt < 2; mt++) {
#pragma unroll
        for (int nt = 0; nt < 4; nt++) {
            const int row0 = mloc + wm * 32 + mt * 16 + g;
            const int col  = nloc + wn * 32 + nt * 8 + 2 * t;
            const float* c = acc[mt][nt];
            if (is_gate) {
                float2 y0, y1;
                y0.x = sigm(c[0]); y0.y = sigm(c[1]);
                y1.x = sigm(c[2]); y1.y = sigm(c[3]);
                *(float2*)&g_gate[row0 * HIDDEN + col] = y0;
                *(float2*)&g_gate[(row0 + 8) * HIDDEN + col] = y1;
            } else {
                float2 y0, y1;
                if (col < 512) {
                    y0.x = tanhf(c[0]); y0.y = tanhf(c[1]);
                    y1.x = tanhf(c[2]); y1.y = tanhf(c[3]);
                } else {
                    y0.x = sigm(c[0]); y0.y = sigm(c[1]);
                    y1.x = sigm(c[2]); y1.y = sigm(c[3]);
                }
                *(float2*)&g_qkv[row0 * QKV_COLS + col] = y0;
                *(float2*)&g_qkv[(row0 + 8) * QKV_COLS + col] = y1;
            }
        }
    }
}

// ---- OUT kernel: out = (z @ Wo^T) * gate ----
__global__ __launch_bounds__(256, 3)
void gemm_out(float* __restrict__ Cout) {
    __shared__ float As[3][BM * BK];
    __shared__ float Bs[3][BN * BK];

    const int nloc = (blockIdx.x & 15) * BN;
    const int mloc = (blockIdx.x >> 4) * BM;

    float acc[2][4][4];
#pragma unroll
    for (int i = 0; i < 2; i++)
#pragma unroll
        for (int j = 0; j < 4; j++)
#pragma unroll
            for (int l = 0; l < 4; l++) acc[i][j][l] = 0.0f;

    gemm_mainloop(As, Bs, g_z, CDIM, g_wor, CDIM, mloc, nloc, CDIM, acc);

    const int tid = threadIdx.x;
    const int warp = tid >> 5, lane = tid & 31;
    const int g = lane >> 2, t = lane & 3;
    const int wm = warp & 1, wn = warp >> 1;

#pragma unroll
    for (int mt = 0; mt < 2; mt++) {
#pragma unroll
        for (int nt = 0; nt < 4; nt++) {
            const int row0 = mloc + wm * 32 + mt * 16 + g;
            const int col  = nloc + wn * 32 + nt * 8 + 2 * t;
            const float* c = acc[mt][nt];
            float2 gt0 = *(const float2*)&g_gate[row0 * HIDDEN + col];
            float2 gt1 = *(const float2*)&g_gate[(row0 + 8) * HIDDEN + col];
            float2 y0, y1;
            y0.x = c[0] * gt0.x; y0.y = c[1] * gt0.y;
            y1.x = c[2] * gt1.x; y1.y = c[3] * gt1.y;
            *(float2*)&Cout[row0 * HIDDEN + col] = y0;
            *(float2*)&Cout[(row0 + 8) * HIDDEN + col] = y1;
        }
    }
}

// ---------------- preround: copy inputs with tf32 (RNA) rounding ----------------
__global__ __launch_bounds__(256)
void preround(const float* __restrict__ hs, const float* __restrict__ Wq,
              const float* __restrict__ Wk, const float* __restrict__ Wv,
              const float* __restrict__ Wo, const float* __restrict__ Wg) {
    constexpr int N_HS = (SEQ * HIDDEN) / 4;          // 1048576
    constexpr int N_W  = (256 * HIDDEN) / 4;          // 131072
    constexpr int TOT  = N_HS * 2 + N_W * 4;          // hs, Wg, Wq, Wk, Wv, Wo

    for (int i = blockIdx.x * blockDim.x + threadIdx.x; i < TOT;
         i += gridDim.x * blockDim.x) {
        const float4* src;
        float4* dst;
        if (i < N_HS) {
            src = (const float4*)hs + i;            dst = (float4*)g_hsr + i;
        } else if (i < 2 * N_HS) {
            src = (const float4*)Wg + (i - N_HS);   dst = (float4*)g_wgr + (i - N_HS);
        } else {
            int j = i - 2 * N_HS;
            if (j < N_W)            { src = (const float4*)Wq + j;           dst = (float4*)g_wqkvr + j; }
            else if (j < 2 * N_W)   { src = (const float4*)Wk + (j - N_W);   dst = (float4*)g_wqkvr + j; }
            else if (j < 3 * N_W)   { src = (const float4*)Wv + (j - 2*N_W); dst = (float4*)g_wqkvr + j; }
            else                    { src = (const float4*)Wo + (j - 3*N_W); dst = (float4*)g_wor + (j - 3*N_W); }
        }
        float4 v = *src;
        v.x = f2tf32(v.x); v.y = f2tf32(v.y); v.z = f2tf32(v.z); v.w = f2tf32(v.w);
        *dst = v;
    }
}

// ---------------- windowed decayed-softmax attention ----------------
// decay 0.45 => bias -0.7985*dist; truncation at W=64 leaves < 1e-21 relative mass.
constexpr int WIN = 64, QB = 128;
constexpr int SROWS = QB + WIN - 1;   // 191
constexpr int PITCH = 9;              // conflict-free scalar smem reads

__global__ __launch_bounds__(128)
void attn_kernel(const float* __restrict__ e0, const float* __restrict__ e1) {
    __shared__ float ks[SROWS * PITCH];
    __shared__ float vs[SROWS * PITCH];

    const int h   = blockIdx.y;
    const int q0  = blockIdx.x * QB;
    const int tid = threadIdx.x;
    const int j0  = q0 - (WIN - 1);

    for (int idx = tid; idx < SROWS * 8; idx += 128) {
        const int r = idx >> 3, c = idx & 7;
        const int j = j0 + r;
        float kv = 0.0f, vv = 0.0f;
        if (j >= 0) {
            kv = g_qkv[j * QKV_COLS + 256 + h * 8 + c];
            vv = g_qkv[j * QKV_COLS + 512 + h * 8 + c];
        }
        ks[r * PITCH + c] = kv;
        vs[r * PITCH + c] = vv;
    }
    __syncthreads();

    const int i = q0 + tid;
    float q[8];
#pragma unroll
    for (int b = 0; b < 8; b++) q[b] = g_qkv[i * QKV_COLS + h * 8 + b];

    float num[8];
#pragma unroll
    for (int b = 0; b < 8; b++) num[b] = 0.0f;
    float den = 0.0f;

    const float LOGD = -0.7985077f;   // ln(0.45)
    const int dmax = (i < WIN - 1) ? i : (WIN - 1);

    for (int d = 0; d <= dmax; d++) {
        const int jj = (tid + (WIN - 1) - d) * PITCH;
        float dot = 0.0f;
#pragma unroll
        for (int b = 0; b < 8; b++) dot += q[b] * ks[jj + b];
        const float w = expf(dot * 0.125f + (float)d * LOGD);
        den += w;
#pragma unroll
        for (int b = 0; b < 8; b++) num[b] += w * vs[jj + b];
    }

    const float inv = 1.0f / den;
#pragma unroll
    for (int b = 0; b < 8; b++) {
        const int c = h * 8 + b;
        const float p = num[b] * inv;
        // write tf32-rounded so gemm_out can consume directly
        g_z[i * CDIM + c] = f2tf32(e1[c] * p + e0[c] * (1.0f - p));
    }
}

// ---------------- launch ----------------
extern "C" void kernel_launch(void* const* d_in, const int* in_sizes, int n_in,
                              void* d_out, int out_size) {
    const float* hs = (const float*)d_in[0];
    const float* Wq = (const float*)d_in[1];
    const float* Wk = (const float*)d_in[2];
    const float* Wv = (const float*)d_in[3];
    const float* Wo = (const float*)d_in[4];
    const float* Wg = (const float*)d_in[5];
    const float* e0 = (const float*)d_in[6];
    const float* e1 = (const float*)d_in[7];
    float* out = (float*)d_out;

    // 0) round all GEMM inputs to tf32 once
    preround<<<1024, 256>>>(hs, Wq, Wk, Wv, Wo, Wg);

    // 1) fused QKV projections (+activations) and gate GEMM (+sigmoid)
    gemm_qkv_gate<<<512 + 192, 256>>>();

    // 2) windowed attention + value-embedding interpolation
    attn_kernel<<<dim3(SEQ / QB, NH), 128>>>(e0, e1);

    // 3) out = (z @ Wo^T) * gate
    gemm_out<<<512, 256>>>(out);
}

// round 9
// speedup vs baseline: 1.6146x; 1.5362x over previous
#include <cuda_runtime.h>
#include <cuda_fp16.h>
#include <cstdint>
#include <math.h>

#define HIDDEN 2048
#define SEQ    2048
#define NH     32
#define QKV_COLS 768   // 256 q | 256 k | 256 v
#define CDIM   256     // N_HEADS * V_BITS

// z is stored scaled by 2^20 (fp16 subnormal avoidance); epilogue multiplies by 2^-20
#define Z_SCALE     1048576.0f
#define Z_SCALE_INV 9.5367431640625e-7f

// ---------------- scratch (static device, no allocations) ----------------
__device__ float  g_qkv[SEQ * QKV_COLS];     // tanh(q) | tanh(k) | sigmoid(v)  (f32)
__device__ __half g_z[SEQ * CDIM];           // attn out * 2^20, fp16
__device__ float  g_gate[SEQ * HIDDEN];      // sigmoid(hs @ Wg^T)
// fp16 copies of GEMM inputs
__device__ __half g_hsr[SEQ * HIDDEN];
__device__ __half g_wgr[HIDDEN * HIDDEN];
__device__ __half g_wqkvr[QKV_COLS * HIDDEN];  // Wq | Wk | Wv concatenated
__device__ __half g_wor[HIDDEN * CDIM];

// ---------------- helpers ----------------
__device__ __forceinline__ void mma16(float* c, const uint32_t* a, const uint32_t* b) {
    asm volatile(
        "mma.sync.aligned.m16n8k16.row.col.f32.f16.f16.f32 "
        "{%0,%1,%2,%3}, {%4,%5,%6,%7}, {%8,%9}, {%0,%1,%2,%3};\n"
        : "+f"(c[0]), "+f"(c[1]), "+f"(c[2]), "+f"(c[3])
        : "r"(a[0]), "r"(a[1]), "r"(a[2]), "r"(a[3]), "r"(b[0]), "r"(b[1]));
}

__device__ __forceinline__ void ldsm4(uint32_t* d, uint32_t addr) {
    asm volatile("ldmatrix.sync.aligned.m8n8.x4.shared.b16 {%0,%1,%2,%3}, [%4];"
                 : "=r"(d[0]), "=r"(d[1]), "=r"(d[2]), "=r"(d[3]) : "r"(addr));
}

__device__ __forceinline__ void cp16(uint32_t dst, const void* src) {
    asm volatile("cp.async.cg.shared.global [%0], [%1], 16;" :: "r"(dst), "l"(src));
}
__device__ __forceinline__ void cp_commit() { asm volatile("cp.async.commit_group;"); }
template <int N>
__device__ __forceinline__ void cp_wait() { asm volatile("cp.async.wait_group %0;" :: "n"(N)); }

__device__ __forceinline__ float sigm(float x) { return 1.0f / (1.0f + expf(-x)); }

// swizzle key over 4 16B-slots per 64B row: distinct permutation per row in each
// bank-parity class -> conflict-free for both producers and ldmatrix phases
__device__ __forceinline__ int swkey(int r) { return (r & 3) ^ ((r & 4) >> 2); }

// ---------------- GEMM (NT: C[M,N] = A[M,K] * B[N,K]^T), fp16 in / f32 acc ----
// CTA tile 128x128x32, 8 warps (2x4), warp tile 64x32, m16n8k16.
// 3-stage cp.async pipeline. Row = 32 halves = 64B = 4 x 16B slots.
constexpr int BM = 128, BN = 128, BK = 32;
constexpr int STAGE = BM * BK * 2;   // 8192 B per operand per stage

__device__ __forceinline__ void gemm_mainloop(
    __half (*As)[BM * BK], __half (*Bs)[BN * BK],
    const __half* __restrict__ Ap, int lda,
    const __half* __restrict__ Bp, int ldb,
    int mloc, int nloc, int K, float acc[4][4][4]) {

    const int tid  = threadIdx.x;
    const int warp = tid >> 5, lane = tid & 31;
    const int wm = warp & 1, wn = warp >> 1;

    // ---- producer: row = tid>>1 (0..127), slots s2,s2+1 ----
    const int pr = tid >> 1;
    const int s2 = (tid & 1) * 2;
    const __half* gA = Ap + (size_t)(mloc + pr) * lda + s2 * 8;
    const __half* gB = Bp + (size_t)(nloc + pr) * ldb + s2 * 8;
    const uint32_t sAb = (uint32_t)__cvta_generic_to_shared(&As[0][0]);
    const uint32_t sBb = (uint32_t)__cvta_generic_to_shared(&Bs[0][0]);
    const int keyp = swkey(pr);
    const uint32_t pa0 = (uint32_t)(pr * 64 + ((s2     ^ keyp) * 16));
    const uint32_t pa1 = (uint32_t)(pr * 64 + (((s2+1) ^ keyp) * 16));

    // ---- consumer (ldmatrix b16, native fp16 fragments) ----
    const int l7    = lane & 7;
    const int keyl  = swkey(l7);
    const int a_row = l7 + ((lane >> 3) & 1) * 8;
    const int a_hb  = lane >> 4;              // k-half (8 halves) within k16 group
    const int b_row = l7 + (lane >> 4) * 8;
    const int b_hb  = (lane >> 3) & 1;
    uint32_t aBase[4], bBase[2];
#pragma unroll
    for (int mt = 0; mt < 4; mt++)
        aBase[mt] = sAb + (uint32_t)((wm * 64 + mt * 16 + a_row) * 64);
#pragma unroll
    for (int p = 0; p < 2; p++)
        bBase[p] = sBb + (uint32_t)((wn * 32 + p * 16 + b_row) * 64);

    const int nk = K / BK;

    // prologue: tiles 0,1 into stages 0,1
#pragma unroll
    for (int p = 0; p < 2; p++) {
        const int off = p * BK;
        const uint32_t sb = (uint32_t)(p * STAGE);
        cp16(sAb + sb + pa0, gA + off);
        cp16(sAb + sb + pa1, gA + off + 8);
        cp16(sBb + sb + pa0, gB + off);
        cp16(sBb + sb + pa1, gB + off + 8);
        cp_commit();
    }

    int st = 0;
    for (int kt = 0; kt < nk; kt++) {
        cp_wait<1>();
        __syncthreads();
        const uint32_t buf = (uint32_t)(st * STAGE);
#pragma unroll
        for (int ks = 0; ks < 2; ks++) {      // two k16 groups per BK=32
            uint32_t afr[4][4];
            uint32_t bfr[2][4];
            const uint32_t aslot = (uint32_t)(((2 * ks + a_hb) ^ keyl) * 16);
            const uint32_t bslot = (uint32_t)(((2 * ks + b_hb) ^ keyl) * 16);
#pragma unroll
            for (int mt = 0; mt < 4; mt++)
                ldsm4(afr[mt], aBase[mt] + buf + aslot);
#pragma unroll
            for (int p = 0; p < 2; p++)
                ldsm4(bfr[p], bBase[p] + buf + bslot);
#pragma unroll
            for (int mt = 0; mt < 4; mt++)
#pragma unroll
                for (int nt = 0; nt < 4; nt++)
                    mma16(acc[mt][nt], afr[mt], &bfr[nt >> 1][(nt & 1) * 2]);
        }
        if (kt + 2 < nk) {
            int stp = st + 2; if (stp >= 3) stp -= 3;
            const int off = (kt + 2) * BK;
            const uint32_t sb = (uint32_t)(stp * STAGE);
            cp16(sAb + sb + pa0, gA + off);
            cp16(sAb + sb + pa1, gA + off + 8);
            cp16(sBb + sb + pa0, gB + off);
            cp16(sBb + sb + pa1, gB + off + 8);
        }
        cp_commit();
        if (++st == 3) st = 0;
    }
}

// ---- fused QKV + GATE kernel ----
__global__ __launch_bounds__(256, 2)
void gemm_qkv_gate() {
    __shared__ __half As[3][BM * BK];
    __shared__ __half Bs[3][BN * BK];

    const int cid = blockIdx.x;
    const __half* Bp;
    int nloc, mloc;
    bool is_gate;
    if (cid < 256) {                  // GATE: 16 x 16 tiles
        is_gate = true;
        nloc = (cid & 15) * BN;
        mloc = (cid >> 4) * BM;
        Bp = g_wgr;
    } else {                          // QKV: 6 x 16 tiles over concat [768,2048]
        is_gate = false;
        const int r = cid - 256;
        nloc = (r % 6) * BN;
        mloc = (r / 6) * BM;
        Bp = g_wqkvr;
    }

    float acc[4][4][4];
#pragma unroll
    for (int i = 0; i < 4; i++)
#pragma unroll
        for (int j = 0; j < 4; j++)
#pragma unroll
            for (int l = 0; l < 4; l++) acc[i][j][l] = 0.0f;

    gemm_mainloop(As, Bs, g_hsr, HIDDEN, Bp, HIDDEN, mloc, nloc, HIDDEN, acc);

    const int tid = threadIdx.x;
    const int warp = tid >> 5, lane = tid & 31;
    const int g = lane >> 2, t = lane & 3;
    const int wm = warp & 1, wn = warp >> 1;

#pragma unroll
    for (int mt = 0; mt < 4; mt++) {
#pragma unroll
        for (int nt = 0; nt < 4; nt++) {
            const int row0 = mloc + wm * 64 + mt * 16 + g;
            const int col  = nloc + wn * 32 + nt * 8 + 2 * t;
            const float* c = acc[mt][nt];
            if (is_gate) {
                float2 y0, y1;
                y0.x = sigm(c[0]); y0.y = sigm(c[1]);
                y1.x = sigm(c[2]); y1.y = sigm(c[3]);
                *(float2*)&g_gate[row0 * HIDDEN + col] = y0;
                *(float2*)&g_gate[(row0 + 8) * HIDDEN + col] = y1;
            } else {
                float2 y0, y1;
                if (col < 512) {
                    y0.x = tanhf(c[0]); y0.y = tanhf(c[1]);
                    y1.x = tanhf(c[2]); y1.y = tanhf(c[3]);
                } else {
                    y0.x = sigm(c[0]); y0.y = sigm(c[1]);
                    y1.x = sigm(c[2]); y1.y = sigm(c[3]);
                }
                *(float2*)&g_qkv[row0 * QKV_COLS + col] = y0;
                *(float2*)&g_qkv[(row0 + 8) * QKV_COLS + col] = y1;
            }
        }
    }
}

// ---- OUT kernel: out = (z * 2^-20 @ Wo^T) * gate ----
__global__ __launch_bounds__(256, 2)
void gemm_out(float* __restrict__ Cout) {
    __shared__ __half As[3][BM * BK];
    __shared__ __half Bs[3][BN * BK];

    const int nloc = (blockIdx.x & 15) * BN;
    const int mloc = (blockIdx.x >> 4) * BM;

    float acc[4][4][4];
#pragma unroll
    for (int i = 0; i < 4; i++)
#pragma unroll
        for (int j = 0; j < 4; j++)
#pragma unroll
            for (int l = 0; l < 4; l++) acc[i][j][l] = 0.0f;

    gemm_mainloop(As, Bs, g_z, CDIM, g_wor, CDIM, mloc, nloc, CDIM, acc);

    const int tid = threadIdx.x;
    const int warp = tid >> 5, lane = tid & 31;
    const int g = lane >> 2, t = lane & 3;
    const int wm = warp & 1, wn = warp >> 1;

#pragma unroll
    for (int mt = 0; mt < 4; mt++) {
#pragma unroll
        for (int nt = 0; nt < 4; nt++) {
            const int row0 = mloc + wm * 64 + mt * 16 + g;
            const int col  = nloc + wn * 32 + nt * 8 + 2 * t;
            const float* c = acc[mt][nt];
            float2 gt0 = *(const float2*)&g_gate[row0 * HIDDEN + col];
            float2 gt1 = *(const float2*)&g_gate[(row0 + 8) * HIDDEN + col];
            float2 y0, y1;
            y0.x = c[0] * Z_SCALE_INV * gt0.x; y0.y = c[1] * Z_SCALE_INV * gt0.y;
            y1.x = c[2] * Z_SCALE_INV * gt1.x; y1.y = c[3] * Z_SCALE_INV * gt1.y;
            *(float2*)&Cout[row0 * HIDDEN + col] = y0;
            *(float2*)&Cout[(row0 + 8) * HIDDEN + col] = y1;
        }
    }
}

// ---------------- preround: convert inputs to fp16 once ----------------
__global__ __launch_bounds__(256)
void preround(const float* __restrict__ hs, const float* __restrict__ Wq,
              const float* __restrict__ Wk, const float* __restrict__ Wv,
              const float* __restrict__ Wo, const float* __restrict__ Wg) {
    constexpr int N_HS = (SEQ * HIDDEN) / 4;          // float4 groups
    constexpr int N_W  = (256 * HIDDEN) / 4;
    constexpr int TOT  = N_HS * 2 + N_W * 4;          // hs, Wg, Wq, Wk, Wv, Wo

    for (int i = blockIdx.x * blockDim.x + threadIdx.x; i < TOT;
         i += gridDim.x * blockDim.x) {
        const float4* src;
        __half* dst;
        int di;
        if (i < N_HS) {
            src = (const float4*)hs + i;            dst = g_hsr;   di = i;
        } else if (i < 2 * N_HS) {
            src = (const float4*)Wg + (i - N_HS);   dst = g_wgr;   di = i - N_HS;
        } else {
            int j = i - 2 * N_HS;
            if (j < N_W)            { src = (const float4*)Wq + j;           dst = g_wqkvr; di = j; }
            else if (j < 2 * N_W)   { src = (const float4*)Wk + (j - N_W);   dst = g_wqkvr; di = j; }
            else if (j < 3 * N_W)   { src = (const float4*)Wv + (j - 2*N_W); dst = g_wqkvr; di = j; }
            else                    { src = (const float4*)Wo + (j - 3*N_W); dst = g_wor;   di = j - 3*N_W; }
        }
        float4 v = *src;
        __half2 h01 = __floats2half2_rn(v.x, v.y);
        __half2 h23 = __floats2half2_rn(v.z, v.w);
        uint2 u;
        u.x = *(uint32_t*)&h01;
        u.y = *(uint32_t*)&h23;
        *(uint2*)&dst[di * 4] = u;
    }
}

// ---------------- windowed decayed-softmax attention ----------------
// decay 0.45 => bias -0.7985*dist; truncation at W=64 leaves < 1e-21 relative mass.
constexpr int WIN = 64, QB = 128;
constexpr int SROWS = QB + WIN - 1;   // 191
constexpr int PITCH = 9;              // conflict-free scalar smem reads

__global__ __launch_bounds__(128)
void attn_kernel(const float* __restrict__ e0, const float* __restrict__ e1) {
    __shared__ float ks[SROWS * PITCH];
    __shared__ float vs[SROWS * PITCH];

    const int h   = blockIdx.y;
    const int q0  = blockIdx.x * QB;
    const int tid = threadIdx.x;
    const int j0  = q0 - (WIN - 1);

    for (int idx = tid; idx < SROWS * 8; idx += 128) {
        const int r = idx >> 3, c = idx & 7;
        const int j = j0 + r;
        float kv = 0.0f, vv = 0.0f;
        if (j >= 0) {
            kv = g_qkv[j * QKV_COLS + 256 + h * 8 + c];
            vv = g_qkv[j * QKV_COLS + 512 + h * 8 + c];
        }
        ks[r * PITCH + c] = kv;
        vs[r * PITCH + c] = vv;
    }
    __syncthreads();

    const int i = q0 + tid;
    float q[8];
#pragma unroll
    for (int b = 0; b < 8; b++) q[b] = g_qkv[i * QKV_COLS + h * 8 + b];

    float num[8];
#pragma unroll
    for (int b = 0; b < 8; b++) num[b] = 0.0f;
    float den = 0.0f;

    const float LOGD = -0.7985077f;   // ln(0.45)
    const int dmax = (i < WIN - 1) ? i : (WIN - 1);

    for (int d = 0; d <= dmax; d++) {
        const int jj = (tid + (WIN - 1) - d) * PITCH;
        float dot = 0.0f;
#pragma unroll
        for (int b = 0; b < 8; b++) dot += q[b] * ks[jj + b];
        const float w = expf(dot * 0.125f + (float)d * LOGD);
        den += w;
#pragma unroll
        for (int b = 0; b < 8; b++) num[b] += w * vs[jj + b];
    }

    const float inv = 1.0f / den;
#pragma unroll
    for (int b = 0; b < 8; b++) {
        const int c = h * 8 + b;
        const float p = num[b] * inv;
        const float z = e1[c] * p + e0[c] * (1.0f - p);
        g_z[i * CDIM + c] = __float2half_rn(z * Z_SCALE);
    }
}

// ---------------- launch ----------------
extern "C" void kernel_launch(void* const* d_in, const int* in_sizes, int n_in,
                              void* d_out, int out_size) {
    const float* hs = (const float*)d_in[0];
    const float* Wq = (const float*)d_in[1];
    const float* Wk = (const float*)d_in[2];
    const float* Wv = (const float*)d_in[3];
    const float* Wo = (const float*)d_in[4];
    const float* Wg = (const float*)d_in[5];
    const float* e0 = (const float*)d_in[6];
    const float* e1 = (const float*)d_in[7];
    float* out = (float*)d_out;

    // 0) convert all GEMM inputs to fp16 once
    preround<<<1024, 256>>>(hs, Wq, Wk, Wv, Wo, Wg);

    // 1) fused QKV projections (+activations) and gate GEMM (+sigmoid)
    gemm_qkv_gate<<<256 + 96, 256>>>();

    // 2) windowed attention + value-embedding interpolation
    attn_kernel<<<dim3(SEQ / QB, NH), 128>>>(e0, e1);

    // 3) out = (z @ Wo^T) * 2^-20 * gate
    gemm_out<<<256, 256>>>(out);
}